// round 7
// baseline (speedup 1.0000x reference)
#include <cuda_runtime.h>
#include <cuda_fp16.h>
#include <cstdint>

// Problem constants (fixed by the dataset)
#define N_PTS   300000
#define INC     128
#define BATCH   4
#define GXD     50
#define GYD     50
#define GZD     4
#define NCELLS  40000          // BATCH*GXD*GYD*GZD
#define NFCH    256            // 2*INC feature channels (cos | sin)

// Scratch (static device globals — no allocation allowed)
__device__ float g_grid[NCELLS * NFCH];     // scatter target [cell][256]
__device__ float g_cnt [NCELLS];            // per-cell point count
__device__ float g_tmp [NCELLS * NFCH];     // y/z box-summed features
__device__ float g_tmpc[NCELLS];            // y/z box-summed counts
__device__ float g_agg [NCELLS * NFCH];     // final per-cell averages
__device__ int   g_binCnt[NCELLS];          // histogram of points per cell
__device__ int   g_binCur[NCELLS];          // allocation cursor (scan result)
__device__ int   g_perm[N_PTS];             // cell-sorted point order

__device__ __forceinline__ int vid_of(int4 cd) {
    return ((cd.w * GXD + (cd.x >> 3)) * GYD + (cd.y >> 3)) * GZD + (cd.z >> 3);
}

// sin/cos: explicit range reduction into [-pi, pi], then HW MUFU intrinsics.
__device__ __forceinline__ void sincos_red(float x, float* s, float* c) {
    float r = x - 6.283185307179586f * rintf(x * 0.15915494309189535f);
    *s = __sinf(r);
    *c = __cosf(r);
}

// Vectorized float4 reduction (PTX ISA 8.1, sm_90+ base feature)
__device__ __forceinline__ void red_add_v4(float* p, float4 v) {
    asm volatile("red.global.add.v4.f32 [%0], {%1, %2, %3, %4};"
                 :: "l"(p), "f"(v.x), "f"(v.y), "f"(v.z), "f"(v.w) : "memory");
}

// ---------------------------------------------------------------------------
// K0: zero the scatter grid + counts + histogram
// ---------------------------------------------------------------------------
__global__ void k_zero() {
    int i = blockIdx.x * blockDim.x + threadIdx.x;
    float4 z = make_float4(0.f, 0.f, 0.f, 0.f);
    if (i < (NCELLS * NFCH) / 4) reinterpret_cast<float4*>(g_grid)[i] = z;
    if (i < NCELLS / 4)          reinterpret_cast<float4*>(g_cnt)[i]  = z;
    if (i < NCELLS)              g_binCnt[i] = 0;
}

// ---------------------------------------------------------------------------
// KS1: histogram points per cell
// ---------------------------------------------------------------------------
__global__ void k_hist(const int* __restrict__ coords) {
    int i = blockIdx.x * blockDim.x + threadIdx.x;
    if (i >= N_PTS) return;
    int4 cd = *reinterpret_cast<const int4*>(&coords[(size_t)i * 4]);
    atomicAdd(&g_binCnt[vid_of(cd)], 1);
}

// ---------------------------------------------------------------------------
// KS2: single-block exclusive scan of g_binCnt -> g_binCur (start offsets)
// ---------------------------------------------------------------------------
#define SCAN_T 1024
#define SCAN_C 40            // elements per thread (1024*40 = 40960 >= 40000)
__global__ void __launch_bounds__(SCAN_T) k_scan() {
    __shared__ int part[SCAN_T];
    int tid  = threadIdx.x;
    int base = tid * SCAN_C;
    int s = 0;
    #pragma unroll
    for (int k = 0; k < SCAN_C; k++) {
        int idx = base + k;
        if (idx < NCELLS) s += g_binCnt[idx];
    }
    part[tid] = s;
    __syncthreads();
    for (int d = 1; d < SCAN_T; d <<= 1) {
        int v = 0;
        if (tid >= d) v = part[tid - d];
        __syncthreads();
        if (tid >= d) part[tid] += v;
        __syncthreads();
    }
    int run = part[tid] - s;   // exclusive prefix of this thread's chunk
    #pragma unroll
    for (int k = 0; k < SCAN_C; k++) {
        int idx = base + k;
        if (idx < NCELLS) {
            g_binCur[idx] = run;
            run += g_binCnt[idx];
        }
    }
}

// ---------------------------------------------------------------------------
// KS3: build permutation (cell-sorted point order)
// ---------------------------------------------------------------------------
__global__ void k_permidx(const int* __restrict__ coords) {
    int i = blockIdx.x * blockDim.x + threadIdx.x;
    if (i >= N_PTS) return;
    int4 cd = *reinterpret_cast<const int4*>(&coords[(size_t)i * 4]);
    int dst = atomicAdd(&g_binCur[vid_of(cd)], 1);
    g_perm[dst] = i;
}

// ---------------------------------------------------------------------------
// K1: mma.sync fp16x3-split GEMM (h = x @ Wm^T) + per-row LayerNorm +
//     sincos + run-aggregated float4 atomic scatter. Points processed in
//     cell-sorted order via g_perm. 512 threads, 128 points/block.
// ---------------------------------------------------------------------------
#define LDA   136                       // halves per smem row (8-half pad)
#define TILE_HALF_BYTES (128 * LDA * 2) // 34816 B per fp16 tile

#define OFF_A_HI  0
#define OFF_A_LO  (OFF_A_HI + TILE_HALF_BYTES)
#define OFF_B_HI  (OFF_A_LO + TILE_HALF_BYTES)
#define OFF_B_LO  (OFF_B_HI + TILE_HALF_BYTES)   // operands end at 139264
#define OFF_COORD (OFF_B_LO + TILE_HALF_BYTES)   // int4[128]  = 2048
#define OFF_VID   (OFF_COORD + 2048)             // int[128]   = 512
#define OFF_GAMMA (OFF_VID + 512)
#define OFF_BETA  (OFF_GAMMA + 512)
#define OFF_WP    (OFF_BETA + 512)               // float[384] = 1536
#define OFF_PS    (OFF_WP + 1536)                // float[128][2] s + [128][2] q = 2048
#define SMEM_BYTES (OFF_PS + 2048)               // 146432

// F staging (reuses operand region after mainloop):
// Hs4[p][phys4], phys4 = (c4 + p) & 63  (float4-granular rotation, p = 0..127)
#define OFF_HS    0                              // 128*64*16 = 131072 <= 139264

__device__ __forceinline__ void mma16816(float* c,
                                         uint32_t a0, uint32_t a1,
                                         uint32_t a2, uint32_t a3,
                                         uint32_t b0, uint32_t b1) {
    asm volatile(
        "mma.sync.aligned.m16n8k16.row.col.f32.f16.f16.f32 "
        "{%0,%1,%2,%3}, {%4,%5,%6,%7}, {%8,%9}, {%0,%1,%2,%3};"
        : "+f"(c[0]), "+f"(c[1]), "+f"(c[2]), "+f"(c[3])
        : "r"(a0), "r"(a1), "r"(a2), "r"(a3), "r"(b0), "r"(b1));
}

// split (v0,v1) into packed half2 hi + half2 lo
__device__ __forceinline__ void cvt_split(float v0, float v1,
                                          uint32_t& hi, uint32_t& lo) {
    __half h0 = __float2half_rn(v0);
    __half h1 = __float2half_rn(v1);
    __half l0 = __float2half_rn(v0 - __half2float(h0));
    __half l1 = __float2half_rn(v1 - __half2float(h1));
    hi = ((uint32_t)__half_as_ushort(h1) << 16) | __half_as_ushort(h0);
    lo = ((uint32_t)__half_as_ushort(l1) << 16) | __half_as_ushort(l0);
}

__global__ void __launch_bounds__(512)
k_gemm_ln_scatter(const float* __restrict__ x,
                  const int*   __restrict__ coords,
                  const float* __restrict__ Wm,
                  const float* __restrict__ gamma,
                  const float* __restrict__ beta,
                  const float* __restrict__ Wp)
{
    extern __shared__ char smraw[];
    __half* AsHi = (__half*)(smraw + OFF_A_HI);
    __half* AsLo = (__half*)(smraw + OFF_A_LO);
    __half* BsHi = (__half*)(smraw + OFF_B_HI);
    __half* BsLo = (__half*)(smraw + OFF_B_LO);
    int4*   sCd  = (int4*)  (smraw + OFF_COORD);
    int*    sVid = (int*)   (smraw + OFF_VID);
    float*  sGa  = (float*) (smraw + OFF_GAMMA);
    float*  sBe  = (float*) (smraw + OFF_BETA);
    float*  sWp  = (float*) (smraw + OFF_WP);
    float*  sPS  = (float*) (smraw + OFF_PS);        // [128][2] sums
    float*  sPQ  = (float*) (smraw + OFF_PS + 1024); // [128][2] sqsums
    float*  Hs   = (float*) (smraw + OFF_HS);
    float4* Hs4  = (float4*)(smraw + OFF_HS);

    const int tid  = threadIdx.x;
    const int row0 = blockIdx.x * 128;

    // ---- Stage operands: 4 threads per row, each does 32 cols (8 float4) ----
    {
        int row = tid >> 2, sel = tid & 3;
        const float4* wrow = (const float4*)(Wm + (size_t)row * 128) + sel * 8;
        #pragma unroll
        for (int q = 0; q < 8; q++) {
            float4 v = wrow[q];
            int c = sel * 32 + q * 4;
            uint32_t hi, lo;
            cvt_split(v.x, v.y, hi, lo);
            *(uint32_t*)(BsHi + row * LDA + c)     = hi;
            *(uint32_t*)(BsLo + row * LDA + c)     = lo;
            cvt_split(v.z, v.w, hi, lo);
            *(uint32_t*)(BsHi + row * LDA + c + 2) = hi;
            *(uint32_t*)(BsLo + row * LDA + c + 2) = lo;
        }
        int sp = row0 + row;                       // sorted position
        int gi = (sp < N_PTS) ? g_perm[sp] : -1;   // original point index
        if (gi >= 0) {
            const float4* xrow = (const float4*)(x + (size_t)gi * 128) + sel * 8;
            #pragma unroll
            for (int q = 0; q < 8; q++) {
                float4 v = xrow[q];
                int c = sel * 32 + q * 4;
                uint32_t hi, lo;
                cvt_split(v.x, v.y, hi, lo);
                *(uint32_t*)(AsHi + row * LDA + c)     = hi;
                *(uint32_t*)(AsLo + row * LDA + c)     = lo;
                cvt_split(v.z, v.w, hi, lo);
                *(uint32_t*)(AsHi + row * LDA + c + 2) = hi;
                *(uint32_t*)(AsLo + row * LDA + c + 2) = lo;
            }
        } else {
            #pragma unroll
            for (int q = 0; q < 8; q++) {
                int c = sel * 32 + q * 4;
                *(uint32_t*)(AsHi + row * LDA + c)     = 0u;
                *(uint32_t*)(AsLo + row * LDA + c)     = 0u;
                *(uint32_t*)(AsHi + row * LDA + c + 2) = 0u;
                *(uint32_t*)(AsLo + row * LDA + c + 2) = 0u;
            }
        }
    }
    // Small params + coords + vid (through the permutation)
    if (tid < 128) {
        sGa[tid] = gamma[tid];
        sBe[tid] = beta[tid];
        #pragma unroll
        for (int q = 0; q < 3; q++) sWp[q * 128 + tid] = Wp[q * 128 + tid];
        int sp = row0 + tid;
        int gi = (sp < N_PTS) ? g_perm[sp] : -1;
        int4 cd = (gi >= 0) ? *reinterpret_cast<const int4*>(&coords[(size_t)gi * 4])
                            : make_int4(0, 0, 0, 0);
        sCd[tid]  = cd;
        sVid[tid] = vid_of(cd);
    }
    __syncthreads();

    // ---- Warp-tiled mainloop: wr = w>>1 owns rows [wr*16,+16), nh = w&1 cols ----
    const int w    = tid >> 5;       // 0..15
    const int lane = tid & 31;
    const int g    = lane >> 2;      // groupID
    const int t    = lane & 3;       // thread-in-group
    const int wr   = w >> 1;         // row group 0..7
    const int nh   = w & 1;          // col half 0..1
    const int w16  = wr * 16;
    const int nb0  = nh * 8;         // first n-tile index (n-tiles of 8 cols)

    float acc[8][4];
    #pragma unroll
    for (int nt = 0; nt < 8; nt++)
        #pragma unroll
        for (int j = 0; j < 4; j++) acc[nt][j] = 0.f;

    #pragma unroll 1
    for (int pass = 0; pass < 3; pass++) {
        const __half* Ap = (pass == 1) ? AsLo : AsHi;
        const __half* Bp = (pass == 2) ? BsLo : BsHi;
        #pragma unroll 2
        for (int k16 = 0; k16 < 8; k16++) {
            const int kk = k16 * 16 + 2 * t;
            uint32_t a0 = *(const uint32_t*)(Ap + (w16 + g)     * LDA + kk);
            uint32_t a1 = *(const uint32_t*)(Ap + (w16 + g + 8) * LDA + kk);
            uint32_t a2 = *(const uint32_t*)(Ap + (w16 + g)     * LDA + kk + 8);
            uint32_t a3 = *(const uint32_t*)(Ap + (w16 + g + 8) * LDA + kk + 8);
            #pragma unroll
            for (int nt = 0; nt < 8; nt++) {
                uint32_t b0 = *(const uint32_t*)(Bp + ((nb0 + nt) * 8 + g) * LDA + kk);
                uint32_t b1 = *(const uint32_t*)(Bp + ((nb0 + nt) * 8 + g) * LDA + kk + 8);
                mma16816(acc[nt], a0, a1, a2, a3, b0, b1);
            }
        }
    }
    __syncthreads();   // all warps done reading operands; Hs may overwrite them

    // ---- LayerNorm stats: partial (64-col) sums, combine across col halves ----
    float s0 = 0.f, q0 = 0.f, s1 = 0.f, q1 = 0.f;
    #pragma unroll
    for (int nt = 0; nt < 8; nt++) {
        s0 += acc[nt][0] + acc[nt][1];
        q0 += acc[nt][0] * acc[nt][0] + acc[nt][1] * acc[nt][1];
        s1 += acc[nt][2] + acc[nt][3];
        q1 += acc[nt][2] * acc[nt][2] + acc[nt][3] * acc[nt][3];
    }
    #pragma unroll
    for (int off = 1; off <= 2; off <<= 1) {
        s0 += __shfl_xor_sync(0xffffffffu, s0, off);
        q0 += __shfl_xor_sync(0xffffffffu, q0, off);
        s1 += __shfl_xor_sync(0xffffffffu, s1, off);
        q1 += __shfl_xor_sync(0xffffffffu, q1, off);
    }
    const int r0l = w16 + g, r1l = r0l + 8;
    if (t == 0) {
        sPS[r0l * 2 + nh] = s0;  sPQ[r0l * 2 + nh] = q0;
        sPS[r1l * 2 + nh] = s1;  sPQ[r1l * 2 + nh] = q1;
    }
    __syncthreads();
    s0 = sPS[r0l * 2] + sPS[r0l * 2 + 1];
    q0 = sPQ[r0l * 2] + sPQ[r0l * 2 + 1];
    s1 = sPS[r1l * 2] + sPS[r1l * 2 + 1];
    q1 = sPQ[r1l * 2] + sPQ[r1l * 2 + 1];
    float mu0 = s0 * (1.f / 128.f), var0 = q0 * (1.f / 128.f) - mu0 * mu0;
    float mu1 = s1 * (1.f / 128.f), var1 = q1 * (1.f / 128.f) - mu1 * mu1;
    float rs0 = rsqrtf(var0 + 1e-6f);
    float rs1 = rsqrtf(var1 + 1e-6f);

    int4 cd0 = sCd[r0l], cd1 = sCd[r1l];
    float fx0 = (float)cd0.x, fy0 = (float)cd0.y, fz0 = (float)cd0.z;
    float fx1 = (float)cd1.x, fy1 = (float)cd1.y, fz1 = (float)cd1.z;

    // ---- F = [h*cos | h*sin] into float4-rotated smem ----
    // channel c lives at Hs[p*256 + (((c>>2)+p)&63)*4 + (c&3)]
    #pragma unroll
    for (int nt = 0; nt < 8; nt++) {
        #pragma unroll
        for (int j = 0; j < 2; j++) {
            int c  = (nb0 + nt) * 8 + 2 * t + j;   // cos channel index (0..127)
            int cs128 = c + 128;                   // sin channel index
            float ga = sGa[c], be = sBe[c];
            float w0 = sWp[c], w1 = sWp[128 + c], w2 = sWp[256 + c];
            {
                float hn = (acc[nt][j] - mu0) * rs0 * ga + be;
                float sn, cs;
                sincos_red(fx0 * w0 + fy0 * w1 + fz0 * w2, &sn, &cs);
                Hs[r0l * 256 + ((((c >> 2) + r0l) & 63) << 2) + (c & 3)]           = hn * cs;
                Hs[r0l * 256 + ((((cs128 >> 2) + r0l) & 63) << 2) + (cs128 & 3)]   = hn * sn;
            }
            {
                float hn = (acc[nt][2 + j] - mu1) * rs1 * ga + be;
                float sn, cs;
                sincos_red(fx1 * w0 + fy1 * w1 + fz1 * w2, &sn, &cs);
                Hs[r1l * 256 + ((((c >> 2) + r1l) & 63) << 2) + (c & 3)]           = hn * cs;
                Hs[r1l * 256 + ((((cs128 >> 2) + r1l) & 63) << 2) + (cs128 & 3)]   = hn * sn;
            }
        }
    }
    // Count channel: one atomic per point
    if (tid < 128 && row0 + tid < N_PTS)
        atomicAdd(&g_cnt[sVid[tid]], 1.0f);

    __syncthreads();

    // ---- Run-aggregated scatter: warp per 8 sorted points; consecutive
    //      points share cells, so accumulate per-run in registers and flush
    //      one red.v4 pair per run. ----
    {
        float4 a0 = make_float4(0.f, 0.f, 0.f, 0.f);
        float4 a1 = make_float4(0.f, 0.f, 0.f, 0.f);
        #pragma unroll 1
        for (int i = 0; i < 8; i++) {
            int p  = w * 8 + i;
            int gp = row0 + p;
            if (gp >= N_PTS) break;          // warp-uniform
            float4 v0 = Hs4[p * 64 + ((lane + p) & 63)];
            float4 v1 = Hs4[p * 64 + ((lane + 32 + p) & 63)];
            a0.x += v0.x; a0.y += v0.y; a0.z += v0.z; a0.w += v0.w;
            a1.x += v1.x; a1.y += v1.y; a1.z += v1.z; a1.w += v1.w;
            bool flush = (i == 7) || (gp + 1 >= N_PTS) || (sVid[p + 1] != sVid[p]);
            if (flush) {
                float* gc = g_grid + (size_t)sVid[p] * NFCH;
                red_add_v4(gc + 4 * lane,       a0);
                red_add_v4(gc + 128 + 4 * lane, a1);
                a0 = make_float4(0.f, 0.f, 0.f, 0.f);
                a1 = make_float4(0.f, 0.f, 0.f, 0.f);
            }
        }
    }
}

// ---------------------------------------------------------------------------
// K2a: 9-point box sum over (y,z), float4 channels. 4 cells per 256-thr block.
// ---------------------------------------------------------------------------
__global__ void k_box_yz() {
    int cell = blockIdx.x * 4 + (threadIdx.x >> 6);
    int ch4  = threadIdx.x & 63;
    int rem  = cell % (GYD * GZD);
    int cy   = rem / GZD;
    int cz   = rem % GZD;
    int dylo = (cy > 0) ? -1 : 0, dyhi = (cy < GYD - 1) ? 1 : 0;
    int dzlo = (cz > 0) ? -1 : 0, dzhi = (cz < GZD - 1) ? 1 : 0;

    const float4* grid4 = (const float4*)g_grid;
    float4 s = make_float4(0.f, 0.f, 0.f, 0.f);
    float  sc = 0.f;
    for (int dy = dylo; dy <= dyhi; dy++)
        for (int dz = dzlo; dz <= dzhi; dz++) {
            int nb = cell + dy * GZD + dz;
            float4 v = grid4[(size_t)nb * 64 + ch4];
            s.x += v.x; s.y += v.y; s.z += v.z; s.w += v.w;
            if (ch4 == 0) sc += g_cnt[nb];
        }
    ((float4*)g_tmp)[(size_t)cell * 64 + ch4] = s;
    if (ch4 == 0) g_tmpc[cell] = sc;
}

// ---------------------------------------------------------------------------
// K2b: 3-point sum over x + divide by count. 4 cells per 256-thread block.
// ---------------------------------------------------------------------------
__global__ void k_box_x_div() {
    int cell = blockIdx.x * 4 + (threadIdx.x >> 6);
    int ch4  = threadIdx.x & 63;
    int cx   = (cell % (GXD * GYD * GZD)) / (GYD * GZD);

    const float4* tmp4 = (const float4*)g_tmp;
    float4 num = make_float4(0.f, 0.f, 0.f, 0.f);
    float  den = 0.f;
    #pragma unroll
    for (int dx = -1; dx <= 1; dx++) {
        int xx = cx + dx;
        if (xx < 0 || xx >= GXD) continue;
        int nb = cell + dx * GYD * GZD;
        float4 v = tmp4[(size_t)nb * 64 + ch4];
        num.x += v.x; num.y += v.y; num.z += v.z; num.w += v.w;
        den += g_tmpc[nb];
    }
    float inv = 1.0f / fmaxf(den, 1e-12f);
    float4 r = make_float4(num.x * inv, num.y * inv, num.z * inv, num.w * inv);
    ((float4*)g_agg)[(size_t)cell * 64 + ch4] = r;
}

// ---------------------------------------------------------------------------
// K3: gather + recombine, float4: warp per point, lane = float4 group (c4g)
// ---------------------------------------------------------------------------
__global__ void k_gather(const int* __restrict__ coords,
                         const float* __restrict__ Wp,
                         float* __restrict__ out)
{
    int tIdx = blockIdx.x * blockDim.x + threadIdx.x;
    int i    = tIdx >> 5;          // point
    int c4g  = tIdx & 31;          // float4 group within 128 channels
    if (i >= N_PTS) return;

    int4 cd = *reinterpret_cast<const int4*>(&coords[(size_t)i * 4]);
    int vid = vid_of(cd);
    float fx = (float)cd.x, fy = (float)cd.y, fz = (float)cd.z;

    const float4* Wp4 = (const float4*)Wp;
    float4 w0 = Wp4[c4g];
    float4 w1 = Wp4[32 + c4g];
    float4 w2 = Wp4[64 + c4g];

    const float4* a = (const float4*)g_agg + (size_t)vid * 64;
    float4 ac = a[c4g];
    float4 as = a[32 + c4g];

    float4 o;
    float sn, cs;
    sincos_red(fx * w0.x + fy * w1.x + fz * w2.x, &sn, &cs);
    o.x = ac.x * cs + as.x * sn;
    sincos_red(fx * w0.y + fy * w1.y + fz * w2.y, &sn, &cs);
    o.y = ac.y * cs + as.y * sn;
    sincos_red(fx * w0.z + fy * w1.z + fz * w2.z, &sn, &cs);
    o.z = ac.z * cs + as.z * sn;
    sincos_red(fx * w0.w + fy * w1.w + fz * w2.w, &sn, &cs);
    o.w = ac.w * cs + as.w * sn;

    ((float4*)out)[(size_t)i * 32 + c4g] = o;
}

// ---------------------------------------------------------------------------
// Launch
// ---------------------------------------------------------------------------
extern "C" void kernel_launch(void* const* d_in, const int* in_sizes, int n_in,
                              void* d_out, int out_size)
{
    const float* x      = (const float*)d_in[0];
    const int*   coords = (const int*)  d_in[1];
    const float* Wm     = (const float*)d_in[2];
    const float* gamma  = (const float*)d_in[3];
    const float* beta   = (const float*)d_in[4];
    const float* Wp     = (const float*)d_in[5];
    float* out = (float*)d_out;

    cudaFuncSetAttribute(k_gemm_ln_scatter,
                         cudaFuncAttributeMaxDynamicSharedMemorySize, SMEM_BYTES);

    k_zero<<<((NCELLS * NFCH) / 4 + 255) / 256, 256>>>();
    k_hist<<<(N_PTS + 255) / 256, 256>>>(coords);
    k_scan<<<1, SCAN_T>>>();
    k_permidx<<<(N_PTS + 255) / 256, 256>>>(coords);
    k_gemm_ln_scatter<<<(N_PTS + 127) / 128, 512, SMEM_BYTES>>>(
        x, coords, Wm, gamma, beta, Wp);
    k_box_yz<<<NCELLS / 4, 256>>>();
    k_box_x_div<<<NCELLS / 4, 256>>>();
    k_gather<<<(N_PTS * 32 + 255) / 256, 256>>>(coords, Wp, out);
}

// round 8
// speedup vs baseline: 1.2089x; 1.2089x over previous
#include <cuda_runtime.h>
#include <cuda_fp16.h>
#include <cstdint>

// Problem constants (fixed by the dataset)
#define N_PTS   300000
#define INC     128
#define BATCH   4
#define GXD     50
#define GYD     50
#define GZD     4
#define NCELLS  40000          // BATCH*GXD*GYD*GZD
#define NFCH    256            // 2*INC feature channels (cos | sin)

// Scratch (static device globals — no allocation allowed)
__device__ float    g_grid[NCELLS * NFCH];  // scatter target [cell][256]
__device__ float    g_cnt [NCELLS];         // per-cell point count
__device__ float    g_tmp [NCELLS * NFCH];  // y/z box-summed features
__device__ float    g_tmpc[NCELLS];         // y/z box-summed counts
__device__ float    g_agg [NCELLS * NFCH];  // final per-cell averages
__device__ uint32_t g_WHi[128 * 64];        // W fp16-split hi (packed half2 words)
__device__ uint32_t g_WLo[128 * 64];        // W fp16-split lo

__device__ __forceinline__ int vid_of(int4 cd) {
    return ((cd.w * GXD + (cd.x >> 3)) * GYD + (cd.y >> 3)) * GZD + (cd.z >> 3);
}

// sin/cos: explicit range reduction into [-pi, pi], then HW MUFU intrinsics.
__device__ __forceinline__ void sincos_red(float x, float* s, float* c) {
    float r = x - 6.283185307179586f * rintf(x * 0.15915494309189535f);
    *s = __sinf(r);
    *c = __cosf(r);
}

// Vectorized float4 reduction (PTX ISA 8.1, sm_90+ base feature)
__device__ __forceinline__ void red_add_v4(float* p, float4 v) {
    asm volatile("red.global.add.v4.f32 [%0], {%1, %2, %3, %4};"
                 :: "l"(p), "f"(v.x), "f"(v.y), "f"(v.z), "f"(v.w) : "memory");
}

// split (v0,v1) into packed half2 hi + half2 lo
__device__ __forceinline__ void cvt_split(float v0, float v1,
                                          uint32_t& hi, uint32_t& lo) {
    __half h0 = __float2half_rn(v0);
    __half h1 = __float2half_rn(v1);
    __half l0 = __float2half_rn(v0 - __half2float(h0));
    __half l1 = __float2half_rn(v1 - __half2float(h1));
    hi = ((uint32_t)__half_as_ushort(h1) << 16) | __half_as_ushort(h0);
    lo = ((uint32_t)__half_as_ushort(l1) << 16) | __half_as_ushort(l0);
}

// ---------------------------------------------------------------------------
// KW: one-shot fp16 split of W (128x128) into packed word arrays
// ---------------------------------------------------------------------------
__global__ void k_wsplit(const float* __restrict__ Wm) {
    int i = blockIdx.x * blockDim.x + threadIdx.x;   // word index 0..8191
    if (i >= 128 * 64) return;
    int row = i >> 6, c2 = i & 63;
    const float2 v = *reinterpret_cast<const float2*>(Wm + (size_t)row * 128 + 2 * c2);
    uint32_t hi, lo;
    cvt_split(v.x, v.y, hi, lo);
    g_WHi[i] = hi;
    g_WLo[i] = lo;
}

// ---------------------------------------------------------------------------
// K0a/K0b: zero the scatter grid + counts (split so GEMM is 4th launch)
// ---------------------------------------------------------------------------
#define HALF_GRID4 ((NCELLS * NFCH) / 8)     // float4 count of half the grid
__global__ void k_zero_a() {
    int i = blockIdx.x * blockDim.x + threadIdx.x;
    if (i < HALF_GRID4)
        reinterpret_cast<float4*>(g_grid)[i] = make_float4(0.f, 0.f, 0.f, 0.f);
}
__global__ void k_zero_b() {
    int i = blockIdx.x * blockDim.x + threadIdx.x;
    float4 z = make_float4(0.f, 0.f, 0.f, 0.f);
    if (i < HALF_GRID4) reinterpret_cast<float4*>(g_grid)[HALF_GRID4 + i] = z;
    if (i < NCELLS / 4) reinterpret_cast<float4*>(g_cnt)[i] = z;
}

// ---------------------------------------------------------------------------
// K1: mma.sync fp16x3-split GEMM (h = x @ Wm^T) + per-row LayerNorm +
//     sincos + float4 vectorized atomic scatter.
//     64 points/CTA, 256 threads (8 warps), ~109 KB smem -> 2 CTAs/SM.
//     Warp w: wr=w>>1 owns rows [wr*16,+16), nh=w&1 owns cols [nh*64,+64).
// ---------------------------------------------------------------------------
#define LDA   136                       // halves per smem row (8-half pad)
#define A_TILE_BYTES (64  * LDA * 2)    // 17408
#define B_TILE_BYTES (128 * LDA * 2)    // 34816

#define OFF_A_HI  0
#define OFF_A_LO  (OFF_A_HI + A_TILE_BYTES)
#define OFF_B_HI  (OFF_A_LO + A_TILE_BYTES)      // 34816
#define OFF_B_LO  (OFF_B_HI + B_TILE_BYTES)      // 69632
#define OFF_COORD (OFF_B_LO + B_TILE_BYTES)      // 104448: int4[64] = 1024
#define OFF_VID   (OFF_COORD + 1024)             // int[64] = 256
#define OFF_GAMMA (OFF_VID + 256)
#define OFF_BETA  (OFF_GAMMA + 512)
#define OFF_WP    (OFF_BETA + 512)               // float[384] = 1536
#define OFF_PS    (OFF_WP + 1536)                // [64][2] s + [64][2] q = 1024
#define SMEM_BYTES (OFF_PS + 1024)               // 109312 -> 2 CTAs/SM

// F staging (reuses operand region after mainloop): Hs[64][256] = 65536 B
#define OFF_HS    0

__device__ __forceinline__ void mma16816(float* c,
                                         uint32_t a0, uint32_t a1,
                                         uint32_t a2, uint32_t a3,
                                         uint32_t b0, uint32_t b1) {
    asm volatile(
        "mma.sync.aligned.m16n8k16.row.col.f32.f16.f16.f32 "
        "{%0,%1,%2,%3}, {%4,%5,%6,%7}, {%8,%9}, {%0,%1,%2,%3};"
        : "+f"(c[0]), "+f"(c[1]), "+f"(c[2]), "+f"(c[3])
        : "r"(a0), "r"(a1), "r"(a2), "r"(a3), "r"(b0), "r"(b1));
}

__global__ void __launch_bounds__(256, 2)
k_gemm_ln_scatter(const float* __restrict__ x,
                  const int*   __restrict__ coords,
                  const float* __restrict__ gamma,
                  const float* __restrict__ beta,
                  const float* __restrict__ Wp)
{
    extern __shared__ char smraw[];
    __half* AsHi = (__half*)(smraw + OFF_A_HI);
    __half* AsLo = (__half*)(smraw + OFF_A_LO);
    __half* BsHi = (__half*)(smraw + OFF_B_HI);
    __half* BsLo = (__half*)(smraw + OFF_B_LO);
    int4*   sCd  = (int4*)  (smraw + OFF_COORD);
    int*    sVid = (int*)   (smraw + OFF_VID);
    float*  sGa  = (float*) (smraw + OFF_GAMMA);
    float*  sBe  = (float*) (smraw + OFF_BETA);
    float*  sWp  = (float*) (smraw + OFF_WP);
    float*  sPS  = (float*) (smraw + OFF_PS);       // [64][2] sums
    float*  sPQ  = (float*) (smraw + OFF_PS + 512); // [64][2] sqsums
    float*  Hs   = (float*) (smraw + OFF_HS);
    float4* Hs4  = (float4*)(smraw + OFF_HS);

    const int tid  = threadIdx.x;
    const int row0 = blockIdx.x * 64;

    // ---- Stage W from pre-split globals (uint2 = 8 halves per iter) ----
    {
        const uint2* whi = (const uint2*)g_WHi;
        const uint2* wlo = (const uint2*)g_WLo;
        #pragma unroll
        for (int it = 0; it < 16; it++) {
            int i2  = it * 256 + tid;          // 0..4095
            int row = i2 >> 5, c4 = i2 & 31;   // 32 uint2 per row (128 halves)
            uint2 h = whi[i2], l = wlo[i2];
            *(uint2*)(BsHi + row * LDA + 4 * c4) = h;
            *(uint2*)(BsLo + row * LDA + 4 * c4) = l;
        }
    }
    // ---- Stage x tile: 4 threads per row, each 32 cols (8 float4) ----
    {
        int row = tid >> 2, sel = tid & 3;     // row 0..63
        int gr = row0 + row;
        if (gr < N_PTS) {
            const float4* xrow = (const float4*)(x + (size_t)gr * 128) + sel * 8;
            #pragma unroll
            for (int q = 0; q < 8; q++) {
                float4 v = xrow[q];
                int c = sel * 32 + q * 4;
                uint32_t hi, lo;
                cvt_split(v.x, v.y, hi, lo);
                *(uint32_t*)(AsHi + row * LDA + c)     = hi;
                *(uint32_t*)(AsLo + row * LDA + c)     = lo;
                cvt_split(v.z, v.w, hi, lo);
                *(uint32_t*)(AsHi + row * LDA + c + 2) = hi;
                *(uint32_t*)(AsLo + row * LDA + c + 2) = lo;
            }
        } else {
            #pragma unroll
            for (int q = 0; q < 8; q++) {
                int c = sel * 32 + q * 4;
                *(uint32_t*)(AsHi + row * LDA + c)     = 0u;
                *(uint32_t*)(AsLo + row * LDA + c)     = 0u;
                *(uint32_t*)(AsHi + row * LDA + c + 2) = 0u;
                *(uint32_t*)(AsLo + row * LDA + c + 2) = 0u;
            }
        }
    }
    // Small params + coords + vid
    if (tid < 128) {
        sGa[tid] = gamma[tid];
        sBe[tid] = beta[tid];
        #pragma unroll
        for (int q = 0; q < 3; q++) sWp[q * 128 + tid] = Wp[q * 128 + tid];
    }
    if (tid < 64) {
        int gr = row0 + tid;
        int4 cd = (gr < N_PTS) ? *reinterpret_cast<const int4*>(&coords[(size_t)gr * 4])
                               : make_int4(0, 0, 0, 0);
        sCd[tid]  = cd;
        sVid[tid] = vid_of(cd);
    }
    __syncthreads();

    // ---- Warp-tiled mainloop ----
    const int w    = tid >> 5;       // 0..7
    const int lane = tid & 31;
    const int g    = lane >> 2;      // groupID
    const int t    = lane & 3;       // thread-in-group
    const int wr   = w >> 1;         // row group 0..3
    const int nh   = w & 1;          // col half 0..1
    const int w16  = wr * 16;
    const int nb0  = nh * 8;         // first n-tile index (n-tiles of 8 cols)

    float acc[8][4];
    #pragma unroll
    for (int nt = 0; nt < 8; nt++)
        #pragma unroll
        for (int j = 0; j < 4; j++) acc[nt][j] = 0.f;

    #pragma unroll 1
    for (int pass = 0; pass < 3; pass++) {
        const __half* Ap = (pass == 1) ? AsLo : AsHi;
        const __half* Bp = (pass == 2) ? BsLo : BsHi;
        #pragma unroll 2
        for (int k16 = 0; k16 < 8; k16++) {
            const int kk = k16 * 16 + 2 * t;
            uint32_t a0 = *(const uint32_t*)(Ap + (w16 + g)     * LDA + kk);
            uint32_t a1 = *(const uint32_t*)(Ap + (w16 + g + 8) * LDA + kk);
            uint32_t a2 = *(const uint32_t*)(Ap + (w16 + g)     * LDA + kk + 8);
            uint32_t a3 = *(const uint32_t*)(Ap + (w16 + g + 8) * LDA + kk + 8);
            #pragma unroll
            for (int nt = 0; nt < 8; nt++) {
                uint32_t b0 = *(const uint32_t*)(Bp + ((nb0 + nt) * 8 + g) * LDA + kk);
                uint32_t b1 = *(const uint32_t*)(Bp + ((nb0 + nt) * 8 + g) * LDA + kk + 8);
                mma16816(acc[nt], a0, a1, a2, a3, b0, b1);
            }
        }
    }
    __syncthreads();   // all warps done reading operands; Hs may overwrite them

    // ---- LayerNorm stats: partial (64-col) sums, combine across col halves ----
    float s0 = 0.f, q0 = 0.f, s1 = 0.f, q1 = 0.f;
    #pragma unroll
    for (int nt = 0; nt < 8; nt++) {
        s0 += acc[nt][0] + acc[nt][1];
        q0 += acc[nt][0] * acc[nt][0] + acc[nt][1] * acc[nt][1];
        s1 += acc[nt][2] + acc[nt][3];
        q1 += acc[nt][2] * acc[nt][2] + acc[nt][3] * acc[nt][3];
    }
    #pragma unroll
    for (int off = 1; off <= 2; off <<= 1) {
        s0 += __shfl_xor_sync(0xffffffffu, s0, off);
        q0 += __shfl_xor_sync(0xffffffffu, q0, off);
        s1 += __shfl_xor_sync(0xffffffffu, s1, off);
        q1 += __shfl_xor_sync(0xffffffffu, q1, off);
    }
    const int r0l = w16 + g, r1l = r0l + 8;
    if (t == 0) {
        sPS[r0l * 2 + nh] = s0;  sPQ[r0l * 2 + nh] = q0;
        sPS[r1l * 2 + nh] = s1;  sPQ[r1l * 2 + nh] = q1;
    }
    __syncthreads();
    s0 = sPS[r0l * 2] + sPS[r0l * 2 + 1];
    q0 = sPQ[r0l * 2] + sPQ[r0l * 2 + 1];
    s1 = sPS[r1l * 2] + sPS[r1l * 2 + 1];
    q1 = sPQ[r1l * 2] + sPQ[r1l * 2 + 1];
    float mu0 = s0 * (1.f / 128.f), var0 = q0 * (1.f / 128.f) - mu0 * mu0;
    float mu1 = s1 * (1.f / 128.f), var1 = q1 * (1.f / 128.f) - mu1 * mu1;
    float rs0 = rsqrtf(var0 + 1e-6f);
    float rs1 = rsqrtf(var1 + 1e-6f);

    int4 cd0 = sCd[r0l], cd1 = sCd[r1l];
    float fx0 = (float)cd0.x, fy0 = (float)cd0.y, fz0 = (float)cd0.z;
    float fx1 = (float)cd1.x, fy1 = (float)cd1.y, fz1 = (float)cd1.z;

    // ---- F = [h*cos | h*sin] into float4-rotated smem ----
    // channel c of point p lives at Hs[p*256 + (((c>>2)+p)&63)*4 + (c&3)]
    #pragma unroll
    for (int nt = 0; nt < 8; nt++) {
        #pragma unroll
        for (int j = 0; j < 2; j++) {
            int c  = (nb0 + nt) * 8 + 2 * t + j;   // cos channel index (0..127)
            int cs128 = c + 128;                   // sin channel index
            float ga = sGa[c], be = sBe[c];
            float w0 = sWp[c], w1 = sWp[128 + c], w2 = sWp[256 + c];
            {
                float hn = (acc[nt][j] - mu0) * rs0 * ga + be;
                float sn, cs;
                sincos_red(fx0 * w0 + fy0 * w1 + fz0 * w2, &sn, &cs);
                Hs[r0l * 256 + ((((c >> 2) + r0l) & 63) << 2) + (c & 3)]           = hn * cs;
                Hs[r0l * 256 + ((((cs128 >> 2) + r0l) & 63) << 2) + (cs128 & 3)]   = hn * sn;
            }
            {
                float hn = (acc[nt][2 + j] - mu1) * rs1 * ga + be;
                float sn, cs;
                sincos_red(fx1 * w0 + fy1 * w1 + fz1 * w2, &sn, &cs);
                Hs[r1l * 256 + ((((c >> 2) + r1l) & 63) << 2) + (c & 3)]           = hn * cs;
                Hs[r1l * 256 + ((((cs128 >> 2) + r1l) & 63) << 2) + (cs128 & 3)]   = hn * sn;
            }
        }
    }
    // Count channel: one atomic per point
    if (tid < 64 && row0 + tid < N_PTS)
        atomicAdd(&g_cnt[sVid[tid]], 1.0f);

    __syncthreads();

    // ---- Vectorized scatter: warp per point (8 points/warp), lane owns
    //      float4 groups c4 = lane and lane+32 ----
    for (int i = 0; i < 8; i++) {
        int p  = w * 8 + i;
        int gp = row0 + p;
        if (gp >= N_PTS) break;          // warp-uniform
        float* gc = g_grid + (size_t)sVid[p] * NFCH;
        float4 v0 = Hs4[p * 64 + ((lane + p) & 63)];
        float4 v1 = Hs4[p * 64 + ((lane + 32 + p) & 63)];
        red_add_v4(gc + 4 * lane,       v0);
        red_add_v4(gc + 128 + 4 * lane, v1);
    }
}

// ---------------------------------------------------------------------------
// K2a: 9-point box sum over (y,z), float4 channels. 4 cells per 256-thr block.
// ---------------------------------------------------------------------------
__global__ void k_box_yz() {
    int cell = blockIdx.x * 4 + (threadIdx.x >> 6);
    int ch4  = threadIdx.x & 63;
    int rem  = cell % (GYD * GZD);
    int cy   = rem / GZD;
    int cz   = rem % GZD;
    int dylo = (cy > 0) ? -1 : 0, dyhi = (cy < GYD - 1) ? 1 : 0;
    int dzlo = (cz > 0) ? -1 : 0, dzhi = (cz < GZD - 1) ? 1 : 0;

    const float4* grid4 = (const float4*)g_grid;
    float4 s = make_float4(0.f, 0.f, 0.f, 0.f);
    float  sc = 0.f;
    for (int dy = dylo; dy <= dyhi; dy++)
        for (int dz = dzlo; dz <= dzhi; dz++) {
            int nb = cell + dy * GZD + dz;
            float4 v = grid4[(size_t)nb * 64 + ch4];
            s.x += v.x; s.y += v.y; s.z += v.z; s.w += v.w;
            if (ch4 == 0) sc += g_cnt[nb];
        }
    ((float4*)g_tmp)[(size_t)cell * 64 + ch4] = s;
    if (ch4 == 0) g_tmpc[cell] = sc;
}

// ---------------------------------------------------------------------------
// K2b: 3-point sum over x + divide by count. 4 cells per 256-thread block.
// ---------------------------------------------------------------------------
__global__ void k_box_x_div() {
    int cell = blockIdx.x * 4 + (threadIdx.x >> 6);
    int ch4  = threadIdx.x & 63;
    int cx   = (cell % (GXD * GYD * GZD)) / (GYD * GZD);

    const float4* tmp4 = (const float4*)g_tmp;
    float4 num = make_float4(0.f, 0.f, 0.f, 0.f);
    float  den = 0.f;
    #pragma unroll
    for (int dx = -1; dx <= 1; dx++) {
        int xx = cx + dx;
        if (xx < 0 || xx >= GXD) continue;
        int nb = cell + dx * GYD * GZD;
        float4 v = tmp4[(size_t)nb * 64 + ch4];
        num.x += v.x; num.y += v.y; num.z += v.z; num.w += v.w;
        den += g_tmpc[nb];
    }
    float inv = 1.0f / fmaxf(den, 1e-12f);
    float4 r = make_float4(num.x * inv, num.y * inv, num.z * inv, num.w * inv);
    ((float4*)g_agg)[(size_t)cell * 64 + ch4] = r;
}

// ---------------------------------------------------------------------------
// K3: gather + recombine, float4: warp per point, lane = float4 group (c4g)
// ---------------------------------------------------------------------------
__global__ void k_gather(const int* __restrict__ coords,
                         const float* __restrict__ Wp,
                         float* __restrict__ out)
{
    int tIdx = blockIdx.x * blockDim.x + threadIdx.x;
    int i    = tIdx >> 5;          // point
    int c4g  = tIdx & 31;          // float4 group within 128 channels
    if (i >= N_PTS) return;

    int4 cd = *reinterpret_cast<const int4*>(&coords[(size_t)i * 4]);
    int vid = vid_of(cd);
    float fx = (float)cd.x, fy = (float)cd.y, fz = (float)cd.z;

    const float4* Wp4 = (const float4*)Wp;
    float4 w0 = Wp4[c4g];
    float4 w1 = Wp4[32 + c4g];
    float4 w2 = Wp4[64 + c4g];

    const float4* a = (const float4*)g_agg + (size_t)vid * 64;
    float4 ac = a[c4g];
    float4 as = a[32 + c4g];

    float4 o;
    float sn, cs;
    sincos_red(fx * w0.x + fy * w1.x + fz * w2.x, &sn, &cs);
    o.x = ac.x * cs + as.x * sn;
    sincos_red(fx * w0.y + fy * w1.y + fz * w2.y, &sn, &cs);
    o.y = ac.y * cs + as.y * sn;
    sincos_red(fx * w0.z + fy * w1.z + fz * w2.z, &sn, &cs);
    o.z = ac.z * cs + as.z * sn;
    sincos_red(fx * w0.w + fy * w1.w + fz * w2.w, &sn, &cs);
    o.w = ac.w * cs + as.w * sn;

    ((float4*)out)[(size_t)i * 32 + c4g] = o;
}

// ---------------------------------------------------------------------------
// Launch (k_gemm_ln_scatter is the 4th launch -> ncu capture slot)
// ---------------------------------------------------------------------------
extern "C" void kernel_launch(void* const* d_in, const int* in_sizes, int n_in,
                              void* d_out, int out_size)
{
    const float* x      = (const float*)d_in[0];
    const int*   coords = (const int*)  d_in[1];
    const float* Wm     = (const float*)d_in[2];
    const float* gamma  = (const float*)d_in[3];
    const float* beta   = (const float*)d_in[4];
    const float* Wp     = (const float*)d_in[5];
    float* out = (float*)d_out;

    cudaFuncSetAttribute(k_gemm_ln_scatter,
                         cudaFuncAttributeMaxDynamicSharedMemorySize, SMEM_BYTES);

    k_wsplit<<<(128 * 64 + 255) / 256, 256>>>(Wm);                 // 1
    k_zero_a<<<(HALF_GRID4 + 255) / 256, 256>>>();                 // 2
    k_zero_b<<<(HALF_GRID4 + 255) / 256, 256>>>();                 // 3
    k_gemm_ln_scatter<<<(N_PTS + 63) / 64, 256, SMEM_BYTES>>>(     // 4 <- ncu
        x, coords, gamma, beta, Wp);
    k_box_yz<<<NCELLS / 4, 256>>>();                               // 5
    k_box_x_div<<<NCELLS / 4, 256>>>();                            // 6
    k_gather<<<(N_PTS * 32 + 255) / 256, 256>>>(coords, Wp, out);  // 7
}

// round 9
// speedup vs baseline: 1.2850x; 1.0629x over previous
#include <cuda_runtime.h>
#include <cuda_fp16.h>
#include <cstdint>

// Problem constants (fixed by the dataset)
#define N_PTS   300000
#define INC     128
#define BATCH   4
#define GXD     50
#define GYD     50
#define GZD     4
#define NCELLS  40000          // BATCH*GXD*GYD*GZD
#define NFCH    256            // 2*INC feature channels (cos | sin)

// Scratch (static device globals — no allocation allowed)
__device__ float    g_grid[NCELLS * NFCH];  // scatter target [cell][256]
__device__ float    g_cnt [NCELLS];         // per-cell point count
__device__ float    g_tmp [NCELLS * NFCH];  // y/z box-summed features
__device__ float    g_tmpc[NCELLS];         // y/z box-summed counts
__device__ float    g_agg [NCELLS * NFCH];  // final per-cell averages
__device__ uint32_t g_WHi[128 * 64];        // W fp16-split hi (packed half2 words)
__device__ uint32_t g_WLo[128 * 64];        // W fp16-split lo

__device__ __forceinline__ int vid_of(int4 cd) {
    return ((cd.w * GXD + (cd.x >> 3)) * GYD + (cd.y >> 3)) * GZD + (cd.z >> 3);
}

// sin/cos: explicit range reduction into [-pi, pi], then HW MUFU intrinsics.
__device__ __forceinline__ void sincos_red(float x, float* s, float* c) {
    float r = x - 6.283185307179586f * rintf(x * 0.15915494309189535f);
    *s = __sinf(r);
    *c = __cosf(r);
}

// Vectorized float4 reduction (PTX ISA 8.1, sm_90+ base feature)
__device__ __forceinline__ void red_add_v4(float* p, float4 v) {
    asm volatile("red.global.add.v4.f32 [%0], {%1, %2, %3, %4};"
                 :: "l"(p), "f"(v.x), "f"(v.y), "f"(v.z), "f"(v.w) : "memory");
}

// split (v0,v1) into packed half2 hi + half2 lo
__device__ __forceinline__ void cvt_split(float v0, float v1,
                                          uint32_t& hi, uint32_t& lo) {
    __half h0 = __float2half_rn(v0);
    __half h1 = __float2half_rn(v1);
    __half l0 = __float2half_rn(v0 - __half2float(h0));
    __half l1 = __float2half_rn(v1 - __half2float(h1));
    hi = ((uint32_t)__half_as_ushort(h1) << 16) | __half_as_ushort(h0);
    lo = ((uint32_t)__half_as_ushort(l1) << 16) | __half_as_ushort(l0);
}

// ---------------------------------------------------------------------------
// KW: one-shot fp16 split of W (128x128) into packed word arrays
// ---------------------------------------------------------------------------
__global__ void k_wsplit(const float* __restrict__ Wm) {
    int i = blockIdx.x * blockDim.x + threadIdx.x;   // word index 0..8191
    if (i >= 128 * 64) return;
    int row = i >> 6, c2 = i & 63;
    const float2 v = *reinterpret_cast<const float2*>(Wm + (size_t)row * 128 + 2 * c2);
    uint32_t hi, lo;
    cvt_split(v.x, v.y, hi, lo);
    g_WHi[i] = hi;
    g_WLo[i] = lo;
}

// ---------------------------------------------------------------------------
// K0a/K0b: zero the scatter grid + counts (split so GEMM is 4th launch)
// ---------------------------------------------------------------------------
#define HALF_GRID4 ((NCELLS * NFCH) / 8)     // float4 count of half the grid
__global__ void k_zero_a() {
    int i = blockIdx.x * blockDim.x + threadIdx.x;
    if (i < HALF_GRID4)
        reinterpret_cast<float4*>(g_grid)[i] = make_float4(0.f, 0.f, 0.f, 0.f);
}
__global__ void k_zero_b() {
    int i = blockIdx.x * blockDim.x + threadIdx.x;
    float4 z = make_float4(0.f, 0.f, 0.f, 0.f);
    if (i < HALF_GRID4) reinterpret_cast<float4*>(g_grid)[HALF_GRID4 + i] = z;
    if (i < NCELLS / 4) reinterpret_cast<float4*>(g_cnt)[i] = z;
}

// ---------------------------------------------------------------------------
// K1: fused fp16x3-split mma.sync GEMM + LayerNorm + sincos + red.v4 scatter.
//     64 points/CTA, 256 threads (8 warps), ~109 KB smem -> 2 CTAs/SM.
//     Warp tile 32 rows x 32 cols: wr = w>>2 (rows [wr*32,+32)),
//     nc = w&3 (cols [nc*32,+32) = n-tiles nc*4+nt, nt=0..3).
//     Single k-loop issues hi*hi + lo*hi + hi*lo per k16 (shared fragments).
// ---------------------------------------------------------------------------
#define LDA   136                       // halves per smem row (8-half pad)
#define A_TILE_BYTES (64  * LDA * 2)    // 17408
#define B_TILE_BYTES (128 * LDA * 2)    // 34816

#define OFF_A_HI  0
#define OFF_A_LO  (OFF_A_HI + A_TILE_BYTES)
#define OFF_B_HI  (OFF_A_LO + A_TILE_BYTES)      // 34816
#define OFF_B_LO  (OFF_B_HI + B_TILE_BYTES)      // 69632
#define OFF_COORD (OFF_B_LO + B_TILE_BYTES)      // 104448: int4[64] = 1024
#define OFF_VID   (OFF_COORD + 1024)             // int[64] = 256
#define OFF_GAMMA (OFF_VID + 256)
#define OFF_BETA  (OFF_GAMMA + 512)
#define OFF_WP    (OFF_BETA + 512)               // float[384] = 1536
#define OFF_PS    (OFF_WP + 1536)                // [64][4] s + [64][4] q = 2048
#define SMEM_BYTES (OFF_PS + 2048)               // 110336 -> 2 CTAs/SM

// F staging (reuses operand region after mainloop): Hs[64][256] = 65536 B
#define OFF_HS    0

__device__ __forceinline__ void mma16816(float* c,
                                         uint32_t a0, uint32_t a1,
                                         uint32_t a2, uint32_t a3,
                                         uint32_t b0, uint32_t b1) {
    asm volatile(
        "mma.sync.aligned.m16n8k16.row.col.f32.f16.f16.f32 "
        "{%0,%1,%2,%3}, {%4,%5,%6,%7}, {%8,%9}, {%0,%1,%2,%3};"
        : "+f"(c[0]), "+f"(c[1]), "+f"(c[2]), "+f"(c[3])
        : "r"(a0), "r"(a1), "r"(a2), "r"(a3), "r"(b0), "r"(b1));
}

__global__ void __launch_bounds__(256, 2)
k_gemm_ln_scatter(const float* __restrict__ x,
                  const int*   __restrict__ coords,
                  const float* __restrict__ gamma,
                  const float* __restrict__ beta,
                  const float* __restrict__ Wp)
{
    extern __shared__ char smraw[];
    __half* AsHi = (__half*)(smraw + OFF_A_HI);
    __half* AsLo = (__half*)(smraw + OFF_A_LO);
    __half* BsHi = (__half*)(smraw + OFF_B_HI);
    __half* BsLo = (__half*)(smraw + OFF_B_LO);
    int4*   sCd  = (int4*)  (smraw + OFF_COORD);
    int*    sVid = (int*)   (smraw + OFF_VID);
    float*  sGa  = (float*) (smraw + OFF_GAMMA);
    float*  sBe  = (float*) (smraw + OFF_BETA);
    float*  sWp  = (float*) (smraw + OFF_WP);
    float*  sPS  = (float*) (smraw + OFF_PS);        // [64][4] partial sums
    float*  sPQ  = (float*) (smraw + OFF_PS + 1024); // [64][4] partial sqsums
    float*  Hs   = (float*) (smraw + OFF_HS);
    float4* Hs4  = (float4*)(smraw + OFF_HS);

    const int tid  = threadIdx.x;
    const int row0 = blockIdx.x * 64;

    // ---- Stage W from pre-split globals (uint2 = 8 halves per iter) ----
    {
        const uint2* whi = (const uint2*)g_WHi;
        const uint2* wlo = (const uint2*)g_WLo;
        #pragma unroll
        for (int it = 0; it < 16; it++) {
            int i2  = it * 256 + tid;          // 0..4095
            int row = i2 >> 5, c4 = i2 & 31;   // 32 uint2 per row (128 halves)
            uint2 h = whi[i2], l = wlo[i2];
            *(uint2*)(BsHi + row * LDA + 4 * c4) = h;
            *(uint2*)(BsLo + row * LDA + 4 * c4) = l;
        }
    }
    // ---- Stage x tile: 4 threads per row, each 32 cols (8 float4) ----
    {
        int row = tid >> 2, sel = tid & 3;     // row 0..63
        int gr = row0 + row;
        if (gr < N_PTS) {
            const float4* xrow = (const float4*)(x + (size_t)gr * 128) + sel * 8;
            #pragma unroll
            for (int q = 0; q < 8; q++) {
                float4 v = xrow[q];
                int c = sel * 32 + q * 4;
                uint32_t hi, lo;
                cvt_split(v.x, v.y, hi, lo);
                *(uint32_t*)(AsHi + row * LDA + c)     = hi;
                *(uint32_t*)(AsLo + row * LDA + c)     = lo;
                cvt_split(v.z, v.w, hi, lo);
                *(uint32_t*)(AsHi + row * LDA + c + 2) = hi;
                *(uint32_t*)(AsLo + row * LDA + c + 2) = lo;
            }
        } else {
            #pragma unroll
            for (int q = 0; q < 8; q++) {
                int c = sel * 32 + q * 4;
                *(uint32_t*)(AsHi + row * LDA + c)     = 0u;
                *(uint32_t*)(AsLo + row * LDA + c)     = 0u;
                *(uint32_t*)(AsHi + row * LDA + c + 2) = 0u;
                *(uint32_t*)(AsLo + row * LDA + c + 2) = 0u;
            }
        }
    }
    // Small params + coords + vid
    if (tid < 128) {
        sGa[tid] = gamma[tid];
        sBe[tid] = beta[tid];
        #pragma unroll
        for (int q = 0; q < 3; q++) sWp[q * 128 + tid] = Wp[q * 128 + tid];
    }
    if (tid < 64) {
        int gr = row0 + tid;
        int4 cd = (gr < N_PTS) ? *reinterpret_cast<const int4*>(&coords[(size_t)gr * 4])
                               : make_int4(0, 0, 0, 0);
        sCd[tid]  = cd;
        sVid[tid] = vid_of(cd);
    }
    __syncthreads();

    // ---- Warp-tiled fused mainloop ----
    const int w    = tid >> 5;       // 0..7
    const int lane = tid & 31;
    const int g    = lane >> 2;      // groupID
    const int t    = lane & 3;       // thread-in-group
    const int wr   = w >> 2;         // row group 0..1 (32 rows each)
    const int nc   = w & 3;          // col group 0..3 (32 cols each)
    const int w32  = wr * 32;
    const int nt0  = nc * 4;         // first n-tile (8-col tiles)

    float acc[2][4][4];              // [m-group][n-tile][frag]
    #pragma unroll
    for (int m = 0; m < 2; m++)
        #pragma unroll
        for (int nt = 0; nt < 4; nt++)
            #pragma unroll
            for (int j = 0; j < 4; j++) acc[m][nt][j] = 0.f;

    #pragma unroll 2
    for (int k16 = 0; k16 < 8; k16++) {
        const int kk = k16 * 16 + 2 * t;
        uint32_t ah[2][4], al[2][4];
        #pragma unroll
        for (int m = 0; m < 2; m++) {
            const int rb = w32 + m * 16;
            ah[m][0] = *(const uint32_t*)(AsHi + (rb + g)     * LDA + kk);
            ah[m][1] = *(const uint32_t*)(AsHi + (rb + g + 8) * LDA + kk);
            ah[m][2] = *(const uint32_t*)(AsHi + (rb + g)     * LDA + kk + 8);
            ah[m][3] = *(const uint32_t*)(AsHi + (rb + g + 8) * LDA + kk + 8);
            al[m][0] = *(const uint32_t*)(AsLo + (rb + g)     * LDA + kk);
            al[m][1] = *(const uint32_t*)(AsLo + (rb + g + 8) * LDA + kk);
            al[m][2] = *(const uint32_t*)(AsLo + (rb + g)     * LDA + kk + 8);
            al[m][3] = *(const uint32_t*)(AsLo + (rb + g + 8) * LDA + kk + 8);
        }
        #pragma unroll
        for (int nt = 0; nt < 4; nt++) {
            const int nrow = (nt0 + nt) * 8 + g;
            uint32_t bh0 = *(const uint32_t*)(BsHi + nrow * LDA + kk);
            uint32_t bh1 = *(const uint32_t*)(BsHi + nrow * LDA + kk + 8);
            uint32_t bl0 = *(const uint32_t*)(BsLo + nrow * LDA + kk);
            uint32_t bl1 = *(const uint32_t*)(BsLo + nrow * LDA + kk + 8);
            #pragma unroll
            for (int m = 0; m < 2; m++) {
                mma16816(acc[m][nt], ah[m][0], ah[m][1], ah[m][2], ah[m][3], bh0, bh1);
                mma16816(acc[m][nt], al[m][0], al[m][1], al[m][2], al[m][3], bh0, bh1);
                mma16816(acc[m][nt], ah[m][0], ah[m][1], ah[m][2], ah[m][3], bl0, bl1);
            }
        }
    }
    __syncthreads();   // all warps done reading operands; Hs may overwrite them

    // ---- LayerNorm stats: 32-col partials, combine across 4 col groups ----
    // Thread rows: r[m][0] = w32 + m*16 + g, r[m][1] = r[m][0] + 8.
    float ps[2][2], pq[2][2];
    #pragma unroll
    for (int m = 0; m < 2; m++) {
        float s0 = 0.f, q0 = 0.f, s1 = 0.f, q1 = 0.f;
        #pragma unroll
        for (int nt = 0; nt < 4; nt++) {
            s0 += acc[m][nt][0] + acc[m][nt][1];
            q0 += acc[m][nt][0] * acc[m][nt][0] + acc[m][nt][1] * acc[m][nt][1];
            s1 += acc[m][nt][2] + acc[m][nt][3];
            q1 += acc[m][nt][2] * acc[m][nt][2] + acc[m][nt][3] * acc[m][nt][3];
        }
        #pragma unroll
        for (int off = 1; off <= 2; off <<= 1) {
            s0 += __shfl_xor_sync(0xffffffffu, s0, off);
            q0 += __shfl_xor_sync(0xffffffffu, q0, off);
            s1 += __shfl_xor_sync(0xffffffffu, s1, off);
            q1 += __shfl_xor_sync(0xffffffffu, q1, off);
        }
        ps[m][0] = s0; pq[m][0] = q0;
        ps[m][1] = s1; pq[m][1] = q1;
    }
    if (t == 0) {
        #pragma unroll
        for (int m = 0; m < 2; m++) {
            int r0 = w32 + m * 16 + g;
            sPS[r0 * 4 + nc]       = ps[m][0];  sPQ[r0 * 4 + nc]       = pq[m][0];
            sPS[(r0 + 8) * 4 + nc] = ps[m][1];  sPQ[(r0 + 8) * 4 + nc] = pq[m][1];
        }
    }
    __syncthreads();

    float mu[2][2], rs[2][2];
    #pragma unroll
    for (int m = 0; m < 2; m++)
        #pragma unroll
        for (int i = 0; i < 2; i++) {
            int r = w32 + m * 16 + g + i * 8;
            float4 s4 = *(const float4*)(sPS + r * 4);
            float4 q4 = *(const float4*)(sPQ + r * 4);
            float s = s4.x + s4.y + s4.z + s4.w;
            float q = q4.x + q4.y + q4.z + q4.w;
            float m0 = s * (1.f / 128.f);
            float v0 = q * (1.f / 128.f) - m0 * m0;
            mu[m][i] = m0;
            rs[m][i] = rsqrtf(v0 + 1e-6f);
        }

    // ---- F = [h*cos | h*sin] into float4-rotated smem, STS.64 pairs ----
    // channel c of point p lives at Hs[p*256 + (((c>>2)+p)&63)*4 + (c&3)]
    #pragma unroll
    for (int m = 0; m < 2; m++) {
        #pragma unroll
        for (int i = 0; i < 2; i++) {
            int r = w32 + m * 16 + g + i * 8;
            int4 cd = sCd[r];
            float fx = (float)cd.x, fy = (float)cd.y, fz = (float)cd.z;
            float muv = mu[m][i], rsv = rs[m][i];
            #pragma unroll
            for (int nt = 0; nt < 4; nt++) {
                int c0 = (nt0 + nt) * 8 + 2 * t;     // even channel of the pair
                float h0 = (acc[m][nt][2 * i]     - muv) * rsv * sGa[c0]     + sBe[c0];
                float h1 = (acc[m][nt][2 * i + 1] - muv) * rsv * sGa[c0 + 1] + sBe[c0 + 1];
                float sn0, cs0, sn1, cs1;
                sincos_red(fx * sWp[c0]     + fy * sWp[128 + c0]     + fz * sWp[256 + c0],     &sn0, &cs0);
                sincos_red(fx * sWp[c0 + 1] + fy * sWp[128 + c0 + 1] + fz * sWp[256 + c0 + 1], &sn1, &cs1);
                // cos pair: channels (c0, c0+1) share the same float4 group
                {
                    float2 pr = make_float2(h0 * cs0, h1 * cs1);
                    *(float2*)(Hs + r * 256 + ((((c0 >> 2) + r) & 63) << 2) + (c0 & 3)) = pr;
                }
                // sin pair: channels (c0+128, c0+129)
                {
                    int cs128 = c0 + 128;
                    float2 pr = make_float2(h0 * sn0, h1 * sn1);
                    *(float2*)(Hs + r * 256 + ((((cs128 >> 2) + r) & 63) << 2) + (cs128 & 3)) = pr;
                }
            }
        }
    }
    // Count channel: one atomic per point
    if (tid < 64 && row0 + tid < N_PTS)
        atomicAdd(&g_cnt[sVid[tid]], 1.0f);

    __syncthreads();

    // ---- Vectorized scatter: warp per point (8 points/warp), lane owns
    //      float4 groups c4 = lane and lane+32 ----
    for (int i = 0; i < 8; i++) {
        int p  = w * 8 + i;
        int gp = row0 + p;
        if (gp >= N_PTS) break;          // warp-uniform
        float* gc = g_grid + (size_t)sVid[p] * NFCH;
        float4 v0 = Hs4[p * 64 + ((lane + p) & 63)];
        float4 v1 = Hs4[p * 64 + ((lane + 32 + p) & 63)];
        red_add_v4(gc + 4 * lane,       v0);
        red_add_v4(gc + 128 + 4 * lane, v1);
    }
}

// ---------------------------------------------------------------------------
// K2a: 9-point box sum over (y,z), float4 channels. 4 cells per 256-thr block.
// ---------------------------------------------------------------------------
__global__ void k_box_yz() {
    int cell = blockIdx.x * 4 + (threadIdx.x >> 6);
    int ch4  = threadIdx.x & 63;
    int rem  = cell % (GYD * GZD);
    int cy   = rem / GZD;
    int cz   = rem % GZD;
    int dylo = (cy > 0) ? -1 : 0, dyhi = (cy < GYD - 1) ? 1 : 0;
    int dzlo = (cz > 0) ? -1 : 0, dzhi = (cz < GZD - 1) ? 1 : 0;

    const float4* grid4 = (const float4*)g_grid;
    float4 s = make_float4(0.f, 0.f, 0.f, 0.f);
    float  sc = 0.f;
    for (int dy = dylo; dy <= dyhi; dy++)
        for (int dz = dzlo; dz <= dzhi; dz++) {
            int nb = cell + dy * GZD + dz;
            float4 v = grid4[(size_t)nb * 64 + ch4];
            s.x += v.x; s.y += v.y; s.z += v.z; s.w += v.w;
            if (ch4 == 0) sc += g_cnt[nb];
        }
    ((float4*)g_tmp)[(size_t)cell * 64 + ch4] = s;
    if (ch4 == 0) g_tmpc[cell] = sc;
}

// ---------------------------------------------------------------------------
// K2b: 3-point sum over x + divide by count. 4 cells per 256-thread block.
// ---------------------------------------------------------------------------
__global__ void k_box_x_div() {
    int cell = blockIdx.x * 4 + (threadIdx.x >> 6);
    int ch4  = threadIdx.x & 63;
    int cx   = (cell % (GXD * GYD * GZD)) / (GYD * GZD);

    const float4* tmp4 = (const float4*)g_tmp;
    float4 num = make_float4(0.f, 0.f, 0.f, 0.f);
    float  den = 0.f;
    #pragma unroll
    for (int dx = -1; dx <= 1; dx++) {
        int xx = cx + dx;
        if (xx < 0 || xx >= GXD) continue;
        int nb = cell + dx * GYD * GZD;
        float4 v = tmp4[(size_t)nb * 64 + ch4];
        num.x += v.x; num.y += v.y; num.z += v.z; num.w += v.w;
        den += g_tmpc[nb];
    }
    float inv = 1.0f / fmaxf(den, 1e-12f);
    float4 r = make_float4(num.x * inv, num.y * inv, num.z * inv, num.w * inv);
    ((float4*)g_agg)[(size_t)cell * 64 + ch4] = r;
}

// ---------------------------------------------------------------------------
// K3: gather + recombine, float4: warp per point, lane = float4 group (c4g)
// ---------------------------------------------------------------------------
__global__ void k_gather(const int* __restrict__ coords,
                         const float* __restrict__ Wp,
                         float* __restrict__ out)
{
    int tIdx = blockIdx.x * blockDim.x + threadIdx.x;
    int i    = tIdx >> 5;          // point
    int c4g  = tIdx & 31;          // float4 group within 128 channels
    if (i >= N_PTS) return;

    int4 cd = *reinterpret_cast<const int4*>(&coords[(size_t)i * 4]);
    int vid = vid_of(cd);
    float fx = (float)cd.x, fy = (float)cd.y, fz = (float)cd.z;

    const float4* Wp4 = (const float4*)Wp;
    float4 w0 = Wp4[c4g];
    float4 w1 = Wp4[32 + c4g];
    float4 w2 = Wp4[64 + c4g];

    const float4* a = (const float4*)g_agg + (size_t)vid * 64;
    float4 ac = a[c4g];
    float4 as = a[32 + c4g];

    float4 o;
    float sn, cs;
    sincos_red(fx * w0.x + fy * w1.x + fz * w2.x, &sn, &cs);
    o.x = ac.x * cs + as.x * sn;
    sincos_red(fx * w0.y + fy * w1.y + fz * w2.y, &sn, &cs);
    o.y = ac.y * cs + as.y * sn;
    sincos_red(fx * w0.z + fy * w1.z + fz * w2.z, &sn, &cs);
    o.z = ac.z * cs + as.z * sn;
    sincos_red(fx * w0.w + fy * w1.w + fz * w2.w, &sn, &cs);
    o.w = ac.w * cs + as.w * sn;

    ((float4*)out)[(size_t)i * 32 + c4g] = o;
}

// ---------------------------------------------------------------------------
// Launch (k_gemm_ln_scatter is the 4th launch -> ncu capture slot)
// ---------------------------------------------------------------------------
extern "C" void kernel_launch(void* const* d_in, const int* in_sizes, int n_in,
                              void* d_out, int out_size)
{
    const float* x      = (const float*)d_in[0];
    const int*   coords = (const int*)  d_in[1];
    const float* Wm     = (const float*)d_in[2];
    const float* gamma  = (const float*)d_in[3];
    const float* beta   = (const float*)d_in[4];
    const float* Wp     = (const float*)d_in[5];
    float* out = (float*)d_out;

    cudaFuncSetAttribute(k_gemm_ln_scatter,
                         cudaFuncAttributeMaxDynamicSharedMemorySize, SMEM_BYTES);

    k_wsplit<<<(128 * 64 + 255) / 256, 256>>>(Wm);                 // 1
    k_zero_a<<<(HALF_GRID4 + 255) / 256, 256>>>();                 // 2
    k_zero_b<<<(HALF_GRID4 + 255) / 256, 256>>>();                 // 3
    k_gemm_ln_scatter<<<(N_PTS + 63) / 64, 256, SMEM_BYTES>>>(     // 4 <- ncu
        x, coords, gamma, beta, Wp);
    k_box_yz<<<NCELLS / 4, 256>>>();                               // 5
    k_box_x_div<<<NCELLS / 4, 256>>>();                            // 6
    k_gather<<<(N_PTS * 32 + 255) / 256, 256>>>(coords, Wp, out);  // 7
}